// round 1
// baseline (speedup 1.0000x reference)
#include <cuda_runtime.h>
#include <cuda_bf16.h>

// Problem constants
#define B_  2
#define N_  2048
#define M_  2048
#define D_  1024
#define H_  16
#define DH_ 64
#define SCALE_ 0.125f   // 64^-0.5

// Scratch (allocation-free rule: __device__ globals)
__device__ float g_Q[B_ * N_ * D_];   // 16 MB  [B*N, H*DH]
__device__ float g_K[B_ * M_ * D_];   // 16 MB
__device__ float g_V[B_ * M_ * D_];   // 16 MB
__device__ float g_O[B_ * N_ * D_];   // 16 MB  attention output, pre-projection

// ---------------------------------------------------------------------------
// SGEMM: C[R,1024] = A[R,1024] @ W[1024,1024] (+ bias)
// 64x64 block tile, BK=16, 256 threads, 4x4 per-thread microtile.
// ---------------------------------------------------------------------------
__global__ __launch_bounds__(256) void gemm_kernel(
    const float* __restrict__ A,
    const float* __restrict__ W,
    const float* __restrict__ bias,   // nullptr -> no bias
    float* __restrict__ C)
{
    const int K = 1024, Nc = 1024;
    __shared__ float As[64][16];
    __shared__ float Ws[16][64];

    const int t  = threadIdx.x;
    const int tx = t & 15;          // 0..15  (N direction, 4 cols each)
    const int ty = t >> 4;          // 0..15  (M direction, 4 rows each)
    const int row0 = blockIdx.y * 64;
    const int col0 = blockIdx.x * 64;

    float acc[4][4] = {};

    // A-tile load coords: thread t -> (row t/4, col (t%4)*4) as float4
    const int ar = t >> 2, ac = (t & 3) << 2;
    // W-tile load coords: thread t -> (row t/16, col (t%16)*4) as float4
    const int wr = t >> 4, wc = (t & 15) << 2;

    for (int k0 = 0; k0 < K; k0 += 16) {
        float4 av = *reinterpret_cast<const float4*>(&A[(size_t)(row0 + ar) * K + k0 + ac]);
        float4 wv = *reinterpret_cast<const float4*>(&W[(size_t)(k0 + wr) * Nc + col0 + wc]);
        *reinterpret_cast<float4*>(&As[ar][ac]) = av;
        *reinterpret_cast<float4*>(&Ws[wr][wc]) = wv;
        __syncthreads();

        #pragma unroll
        for (int kk = 0; kk < 16; kk++) {
            float a0 = As[ty * 4 + 0][kk];
            float a1 = As[ty * 4 + 1][kk];
            float a2 = As[ty * 4 + 2][kk];
            float a3 = As[ty * 4 + 3][kk];
            float4 b = *reinterpret_cast<const float4*>(&Ws[kk][tx * 4]);
            acc[0][0] += a0 * b.x; acc[0][1] += a0 * b.y; acc[0][2] += a0 * b.z; acc[0][3] += a0 * b.w;
            acc[1][0] += a1 * b.x; acc[1][1] += a1 * b.y; acc[1][2] += a1 * b.z; acc[1][3] += a1 * b.w;
            acc[2][0] += a2 * b.x; acc[2][1] += a2 * b.y; acc[2][2] += a2 * b.z; acc[2][3] += a2 * b.w;
            acc[3][0] += a3 * b.x; acc[3][1] += a3 * b.y; acc[3][2] += a3 * b.z; acc[3][3] += a3 * b.w;
        }
        __syncthreads();
    }

    float4 bv = make_float4(0.f, 0.f, 0.f, 0.f);
    if (bias != nullptr)
        bv = *reinterpret_cast<const float4*>(&bias[col0 + tx * 4]);

    #pragma unroll
    for (int i = 0; i < 4; i++) {
        float4 o;
        o.x = acc[i][0] + bv.x;
        o.y = acc[i][1] + bv.y;
        o.z = acc[i][2] + bv.z;
        o.w = acc[i][3] + bv.w;
        *reinterpret_cast<float4*>(&C[(size_t)(row0 + ty * 4 + i) * Nc + col0 + tx * 4]) = o;
    }
}

// ---------------------------------------------------------------------------
// Flash attention: each thread owns one query row (softmax fully thread-local).
// Block: 128 threads = 128 queries of one (b, h). K/V staged in smem tiles of
// 32 keys; scores & accumulators live in registers.
// grid = (N/128, H, B)
// ---------------------------------------------------------------------------
#define KT 32

__global__ __launch_bounds__(128) void attn_kernel()
{
    __shared__ float Ks[KT * DH_];   // 8 KB
    __shared__ float Vs[KT * DH_];   // 8 KB

    const int t  = threadIdx.x;
    const int q0 = blockIdx.x * 128;
    const int h  = blockIdx.y;
    const int b  = blockIdx.z;

    // Load this thread's query row (pre-scaled)
    const float* Qrow = &g_Q[(size_t)(b * N_ + q0 + t) * D_ + h * DH_];
    float q[DH_];
    #pragma unroll
    for (int i = 0; i < DH_ / 4; i++) {
        float4 v = *reinterpret_cast<const float4*>(&Qrow[i * 4]);
        q[i * 4 + 0] = v.x * SCALE_;
        q[i * 4 + 1] = v.y * SCALE_;
        q[i * 4 + 2] = v.z * SCALE_;
        q[i * 4 + 3] = v.w * SCALE_;
    }

    float acc[DH_];
    #pragma unroll
    for (int d = 0; d < DH_; d++) acc[d] = 0.f;
    float mmax = -1e30f;
    float lsum = 0.f;

    #pragma unroll 1
    for (int m0 = 0; m0 < M_; m0 += KT) {
        // Cooperative K/V tile load: KT*DH floats = 512 float4s, 128 thr -> 4 each
        #pragma unroll
        for (int i = 0; i < 4; i++) {
            int f = t + i * 128;          // float4 index
            int j = f >> 4;               // key row within tile
            int c = (f & 15) << 2;        // float offset within row
            size_t gidx = (size_t)(b * M_ + m0 + j) * D_ + h * DH_ + c;
            *reinterpret_cast<float4*>(&Ks[j * DH_ + c]) =
                *reinterpret_cast<const float4*>(&g_K[gidx]);
            *reinterpret_cast<float4*>(&Vs[j * DH_ + c]) =
                *reinterpret_cast<const float4*>(&g_V[gidx]);
        }
        __syncthreads();

        // Scores for KT keys (broadcast smem reads across the warp)
        float s[KT];
        float tilemax = -1e30f;
        #pragma unroll
        for (int j = 0; j < KT; j++) {
            const float4* kr = reinterpret_cast<const float4*>(&Ks[j * DH_]);
            float d0 = 0.f;
            #pragma unroll
            for (int i = 0; i < DH_ / 4; i++) {
                float4 kv = kr[i];
                d0 += q[4 * i + 0] * kv.x + q[4 * i + 1] * kv.y
                    + q[4 * i + 2] * kv.z + q[4 * i + 3] * kv.w;
            }
            s[j] = d0;
            tilemax = fmaxf(tilemax, d0);
        }

        // Online softmax update
        float mnew = fmaxf(mmax, tilemax);
        float corr = __expf(mmax - mnew);
        lsum *= corr;
        #pragma unroll
        for (int d = 0; d < DH_; d++) acc[d] *= corr;

        #pragma unroll
        for (int j = 0; j < KT; j++) {
            float p = __expf(s[j] - mnew);
            lsum += p;
            const float4* vr = reinterpret_cast<const float4*>(&Vs[j * DH_]);
            #pragma unroll
            for (int i = 0; i < DH_ / 4; i++) {
                float4 vv = vr[i];
                acc[4 * i + 0] += p * vv.x;
                acc[4 * i + 1] += p * vv.y;
                acc[4 * i + 2] += p * vv.z;
                acc[4 * i + 3] += p * vv.w;
            }
        }
        mmax = mnew;
        __syncthreads();
    }

    float inv = 1.f / lsum;
    float* Orow = &g_O[(size_t)(b * N_ + q0 + t) * D_ + h * DH_];
    #pragma unroll
    for (int i = 0; i < DH_ / 4; i++) {
        float4 o;
        o.x = acc[4 * i + 0] * inv;
        o.y = acc[4 * i + 1] * inv;
        o.z = acc[4 * i + 2] * inv;
        o.w = acc[4 * i + 3] * inv;
        *reinterpret_cast<float4*>(&Orow[i * 4]) = o;
    }
}

// ---------------------------------------------------------------------------
// Launch: Q/K/V projections -> attention -> output projection (+bias)
// All launches on the default stream; no sync, no allocation (capture-safe).
// ---------------------------------------------------------------------------
extern "C" void kernel_launch(void* const* d_in, const int* in_sizes, int n_in,
                              void* d_out, int out_size)
{
    const float* x   = (const float*)d_in[0];
    const float* ctx = (const float*)d_in[1];
    const float* Wq  = (const float*)d_in[2];
    const float* Wk  = (const float*)d_in[3];
    const float* Wv  = (const float*)d_in[4];
    const float* Wo  = (const float*)d_in[5];
    const float* bo  = (const float*)d_in[6];
    float* out = (float*)d_out;

    float *Qp, *Kp, *Vp, *Op;
    cudaGetSymbolAddress((void**)&Qp, g_Q);
    cudaGetSymbolAddress((void**)&Kp, g_K);
    cudaGetSymbolAddress((void**)&Vp, g_V);
    cudaGetSymbolAddress((void**)&Op, g_O);

    dim3 gblock(256);
    dim3 ggrid(1024 / 64, 4096 / 64);   // (Ncols/64, Rows/64)

    gemm_kernel<<<ggrid, gblock>>>(x,   Wq, nullptr, Qp);
    gemm_kernel<<<ggrid, gblock>>>(ctx, Wk, nullptr, Kp);
    gemm_kernel<<<ggrid, gblock>>>(ctx, Wv, nullptr, Vp);

    attn_kernel<<<dim3(N_ / 128, H_, B_), 128>>>();

    gemm_kernel<<<ggrid, gblock>>>(Op, Wo, bo, out);
}

// round 3
// speedup vs baseline: 1.3095x; 1.3095x over previous
#include <cuda_runtime.h>
#include <cuda_bf16.h>
#include <cstdint>

// ---------------------------------------------------------------------------
// Problem constants
// ---------------------------------------------------------------------------
#define B_  2
#define N_  2048
#define M_  2048
#define D_  1024
#define H_  16
#define DH_ 64
#define SCALE_ 0.125f
#define ROWS_ (B_ * N_)   // 4096

// ---------------------------------------------------------------------------
// Portable PTX helpers (sm_80+ features only — valid at compute_103)
// ---------------------------------------------------------------------------
__device__ __forceinline__ uint32_t smem_u32(const void* p) {
    uint32_t a;
    asm("{ .reg .u64 t; cvta.to.shared.u64 t, %1; cvt.u32.u64 %0, t; }" : "=r"(a) : "l"(p));
    return a;
}
#define CP_ASYNC16(sa, ga) \
    asm volatile("cp.async.cg.shared.global [%0], [%1], 16;" :: "r"(sa), "l"(ga))
#define CP_COMMIT() asm volatile("cp.async.commit_group;" ::: "memory")
#define CP_WAIT(n)  asm volatile("cp.async.wait_group %0;" :: "n"(n) : "memory")

__device__ __forceinline__ void ldsm_x4(uint32_t* r, uint32_t addr) {
    asm volatile("ldmatrix.sync.aligned.m8n8.x4.shared.b16 {%0,%1,%2,%3}, [%4];"
                 : "=r"(r[0]), "=r"(r[1]), "=r"(r[2]), "=r"(r[3]) : "r"(addr));
}
__device__ __forceinline__ void mma16816(float* c, const uint32_t* a, const uint32_t* b) {
    asm volatile(
        "mma.sync.aligned.m16n8k16.row.col.f32.bf16.bf16.f32 "
        "{%0,%1,%2,%3}, {%4,%5,%6,%7}, {%8,%9}, {%0,%1,%2,%3};"
        : "+f"(c[0]), "+f"(c[1]), "+f"(c[2]), "+f"(c[3])
        : "r"(a[0]), "r"(a[1]), "r"(a[2]), "r"(a[3]), "r"(b[0]), "r"(b[1]));
}

// ---------------------------------------------------------------------------
// Scratch (__device__ globals)
// ---------------------------------------------------------------------------
__device__ float g_Q[ROWS_ * D_];
__device__ float g_K[ROWS_ * D_];
__device__ float g_V[ROWS_ * D_];
__device__ float g_O[ROWS_ * D_];

__device__ __nv_bfloat16 g_xh[ROWS_ * D_], g_xl[ROWS_ * D_];
__device__ __nv_bfloat16 g_ch[ROWS_ * D_], g_cl[ROWS_ * D_];
__device__ __nv_bfloat16 g_oh[ROWS_ * D_], g_ol[ROWS_ * D_];
__device__ __nv_bfloat16 g_wh[4][D_ * D_], g_wl[4][D_ * D_];  // q,k,v,o transposed [n][k]

// ---------------------------------------------------------------------------
// fp32 -> bf16 hi/lo split
// ---------------------------------------------------------------------------
__global__ void split_kernel(const float* __restrict__ src,
                             __nv_bfloat16* __restrict__ hi,
                             __nv_bfloat16* __restrict__ lo, int n)
{
    int i = blockIdx.x * blockDim.x + threadIdx.x;
    if (i < n) {
        float a = src[i];
        __nv_bfloat16 h = __float2bfloat16(a);
        hi[i] = h;
        lo[i] = __float2bfloat16(a - __bfloat162float(h));
    }
}

// fp32 W[k][n] -> bf16 hi/lo transposed out[n][k]
__global__ void wsplit_t_kernel(const float* __restrict__ W,
                                __nv_bfloat16* __restrict__ hi,
                                __nv_bfloat16* __restrict__ lo)
{
    __shared__ float tile[32][33];
    int n0 = blockIdx.x * 32, k0 = blockIdx.y * 32;
    tile[threadIdx.y][threadIdx.x] = W[(size_t)(k0 + threadIdx.y) * D_ + n0 + threadIdx.x];
    __syncthreads();
    float a = tile[threadIdx.x][threadIdx.y];
    __nv_bfloat16 h = __float2bfloat16(a);
    size_t o = (size_t)(n0 + threadIdx.y) * D_ + k0 + threadIdx.x;
    hi[o] = h;
    lo[o] = __float2bfloat16(a - __bfloat162float(h));
}

// ---------------------------------------------------------------------------
// HMMA GEMM: C[4096,1024] = A @ B^T (B stored [n][k]), bf16 split-3, fp32 acc
// CTA 128x128, 8 warps (warp tile 32x64), K-stage 32, cp.async double buffer.
// smem row stride 80B -> ldmatrix conflict-free (r*80 mod 128 distinct, r=0..7)
// ---------------------------------------------------------------------------
#define NSTG (D_ / 32)          // 32 stages
#define ARR_STRIDE 10240        // 128 rows * 80B
#define STAGE_STRIDE (4 * ARR_STRIDE)   // Ah,Al,Bh,Bl
#define GEMM_SMEM (2 * STAGE_STRIDE)    // 81920

__global__ __launch_bounds__(256) void hmma_gemm(
    const __nv_bfloat16* __restrict__ Ah_g, const __nv_bfloat16* __restrict__ Al_g,
    const __nv_bfloat16* __restrict__ Bh_g, const __nv_bfloat16* __restrict__ Bl_g,
    const float* __restrict__ bias,
    float* __restrict__ C)
{
    extern __shared__ char smem[];
    const uint32_t sb = smem_u32(smem);
    const int t = threadIdx.x;
    const int l = t & 31;
    const int wid = t >> 5;
    const int row0 = blockIdx.y * 128;
    const int col0 = blockIdx.x * 128;
    const int wr0 = (wid & 3) * 32;     // warp row offset within CTA tile
    const int wc0 = (wid >> 2) * 64;    // warp col offset within CTA tile

    float acc[2][8][4];
    #pragma unroll
    for (int i = 0; i < 2; i++)
        #pragma unroll
        for (int j = 0; j < 8; j++)
            #pragma unroll
            for (int k = 0; k < 4; k++) acc[i][j][k] = 0.f;

    // per-thread load coords (8 x 16B per thread per stage)
    // idx = i*256 + t ; arr = idx/512 ; row = (idx%512)/4 ; chunk = idx%4
    auto load_stage = [&](int s) {
        const int k0 = s * 32;
        const uint32_t sbase = sb + (s & 1) * STAGE_STRIDE;
        #pragma unroll
        for (int i = 0; i < 8; i++) {
            int idx = i * 256 + t;
            int arr = idx >> 9;
            int rem = idx & 511;
            int row = rem >> 2;
            int ch  = rem & 3;
            const __nv_bfloat16* g;
            if (arr == 0)      g = Ah_g + (size_t)(row0 + row) * D_ + k0 + ch * 8;
            else if (arr == 1) g = Al_g + (size_t)(row0 + row) * D_ + k0 + ch * 8;
            else if (arr == 2) g = Bh_g + (size_t)(col0 + row) * D_ + k0 + ch * 8;
            else               g = Bl_g + (size_t)(col0 + row) * D_ + k0 + ch * 8;
            uint32_t sa = sbase + arr * ARR_STRIDE + row * 80 + ch * 16;
            CP_ASYNC16(sa, g);
        }
        CP_COMMIT();
    };

    load_stage(0);

    for (int s = 0; s < NSTG; s++) {
        if (s + 1 < NSTG) { load_stage(s + 1); CP_WAIT(1); }
        else              { CP_WAIT(0); }
        __syncthreads();

        const uint32_t base = sb + (s & 1) * STAGE_STRIDE;
        const uint32_t aAh = base;
        const uint32_t aAl = base + ARR_STRIDE;
        const uint32_t aBh = base + 2 * ARR_STRIDE;
        const uint32_t aBl = base + 3 * ARR_STRIDE;

        #pragma unroll
        for (int ks = 0; ks < 2; ks++) {
            uint32_t ah[2][4], al[2][4], bh[8][2], bl[8][2];
            // A fragments: lane -> row (l&15), k-chunk (l>>4)
            {
                int ar = wr0 + (l & 15);
                int ac = 2 * ks + (l >> 4);
                ldsm_x4(ah[0], aAh + (uint32_t)(ar * 80 + ac * 16));
                ldsm_x4(ah[1], aAh + (uint32_t)((ar + 16) * 80 + ac * 16));
                ldsm_x4(al[0], aAl + (uint32_t)(ar * 80 + ac * 16));
                ldsm_x4(al[1], aAl + (uint32_t)((ar + 16) * 80 + ac * 16));
            }
            // B fragments: x4 covers two n8 tiles
            {
                int br = wc0 + ((l >> 4) << 3) + (l & 7);
                int bc = 2 * ks + ((l >> 3) & 1);
                #pragma unroll
                for (int nt2 = 0; nt2 < 4; nt2++) {
                    uint32_t r[4];
                    ldsm_x4(r, aBh + (uint32_t)((br + nt2 * 16) * 80 + bc * 16));
                    bh[2 * nt2][0] = r[0]; bh[2 * nt2][1] = r[1];
                    bh[2 * nt2 + 1][0] = r[2]; bh[2 * nt2 + 1][1] = r[3];
                    ldsm_x4(r, aBl + (uint32_t)((br + nt2 * 16) * 80 + bc * 16));
                    bl[2 * nt2][0] = r[0]; bl[2 * nt2][1] = r[1];
                    bl[2 * nt2 + 1][0] = r[2]; bl[2 * nt2 + 1][1] = r[3];
                }
            }
            #pragma unroll
            for (int mt = 0; mt < 2; mt++)
                #pragma unroll
                for (int nt = 0; nt < 8; nt++) {
                    mma16816(acc[mt][nt], ah[mt], bh[nt]);
                    mma16816(acc[mt][nt], ah[mt], bl[nt]);
                    mma16816(acc[mt][nt], al[mt], bh[nt]);
                }
        }
        __syncthreads();
    }

    // Epilogue: acc fragment rows m=(l>>2)+{0,8}, cols n=(l&3)*2+{0,1}
    #pragma unroll
    for (int mt = 0; mt < 2; mt++)
        #pragma unroll
        for (int nt = 0; nt < 8; nt++) {
            int m = row0 + wr0 + mt * 16 + (l >> 2);
            int n = col0 + wc0 + nt * 8 + (l & 3) * 2;
            float bx = 0.f, by = 0.f;
            if (bias != nullptr) { bx = bias[n]; by = bias[n + 1]; }
            float2 v0 = make_float2(acc[mt][nt][0] + bx, acc[mt][nt][1] + by);
            float2 v1 = make_float2(acc[mt][nt][2] + bx, acc[mt][nt][3] + by);
            *reinterpret_cast<float2*>(&C[(size_t)m * D_ + n]) = v0;
            *reinterpret_cast<float2*>(&C[(size_t)(m + 8) * D_ + n]) = v1;
        }
}

// ---------------------------------------------------------------------------
// Flash attention (FFMA, unchanged): one query row per thread
// ---------------------------------------------------------------------------
#define KT 32

__global__ __launch_bounds__(128) void attn_kernel()
{
    __shared__ float Ks[KT * DH_];
    __shared__ float Vs[KT * DH_];

    const int t  = threadIdx.x;
    const int q0 = blockIdx.x * 128;
    const int h  = blockIdx.y;
    const int b  = blockIdx.z;

    const float* Qrow = &g_Q[(size_t)(b * N_ + q0 + t) * D_ + h * DH_];
    float q[DH_];
    #pragma unroll
    for (int i = 0; i < DH_ / 4; i++) {
        float4 v = *reinterpret_cast<const float4*>(&Qrow[i * 4]);
        q[i * 4 + 0] = v.x * SCALE_;
        q[i * 4 + 1] = v.y * SCALE_;
        q[i * 4 + 2] = v.z * SCALE_;
        q[i * 4 + 3] = v.w * SCALE_;
    }

    float acc[DH_];
    #pragma unroll
    for (int d = 0; d < DH_; d++) acc[d] = 0.f;
    float mmax = -1e30f, lsum = 0.f;

    #pragma unroll 1
    for (int m0 = 0; m0 < M_; m0 += KT) {
        #pragma unroll
        for (int i = 0; i < 4; i++) {
            int f = t + i * 128;
            int j = f >> 4;
            int c = (f & 15) << 2;
            size_t gidx = (size_t)(b * M_ + m0 + j) * D_ + h * DH_ + c;
            *reinterpret_cast<float4*>(&Ks[j * DH_ + c]) =
                *reinterpret_cast<const float4*>(&g_K[gidx]);
            *reinterpret_cast<float4*>(&Vs[j * DH_ + c]) =
                *reinterpret_cast<const float4*>(&g_V[gidx]);
        }
        __syncthreads();

        float s[KT];
        float tilemax = -1e30f;
        #pragma unroll
        for (int j = 0; j < KT; j++) {
            const float4* kr = reinterpret_cast<const float4*>(&Ks[j * DH_]);
            float d0 = 0.f;
            #pragma unroll
            for (int i = 0; i < DH_ / 4; i++) {
                float4 kv = kr[i];
                d0 += q[4 * i + 0] * kv.x + q[4 * i + 1] * kv.y
                    + q[4 * i + 2] * kv.z + q[4 * i + 3] * kv.w;
            }
            s[j] = d0;
            tilemax = fmaxf(tilemax, d0);
        }

        float mnew = fmaxf(mmax, tilemax);
        float corr = __expf(mmax - mnew);
        lsum *= corr;
        #pragma unroll
        for (int d = 0; d < DH_; d++) acc[d] *= corr;

        #pragma unroll
        for (int j = 0; j < KT; j++) {
            float p = __expf(s[j] - mnew);
            lsum += p;
            const float4* vr = reinterpret_cast<const float4*>(&Vs[j * DH_]);
            #pragma unroll
            for (int i = 0; i < DH_ / 4; i++) {
                float4 vv = vr[i];
                acc[4 * i + 0] += p * vv.x;
                acc[4 * i + 1] += p * vv.y;
                acc[4 * i + 2] += p * vv.z;
                acc[4 * i + 3] += p * vv.w;
            }
        }
        mmax = mnew;
        __syncthreads();
    }

    float inv = 1.f / lsum;
    float* Orow = &g_O[(size_t)(b * N_ + q0 + t) * D_ + h * DH_];
    #pragma unroll
    for (int i = 0; i < DH_ / 4; i++) {
        float4 o;
        o.x = acc[4 * i + 0] * inv;
        o.y = acc[4 * i + 1] * inv;
        o.z = acc[4 * i + 2] * inv;
        o.w = acc[4 * i + 3] * inv;
        *reinterpret_cast<float4*>(&Orow[i * 4]) = o;
    }
}

// ---------------------------------------------------------------------------
// Launch
// ---------------------------------------------------------------------------
extern "C" void kernel_launch(void* const* d_in, const int* in_sizes, int n_in,
                              void* d_out, int out_size)
{
    const float* x   = (const float*)d_in[0];
    const float* ctx = (const float*)d_in[1];
    const float* Wq  = (const float*)d_in[2];
    const float* Wk  = (const float*)d_in[3];
    const float* Wv  = (const float*)d_in[4];
    const float* Wo  = (const float*)d_in[5];
    const float* bo  = (const float*)d_in[6];
    float* out = (float*)d_out;

    float *Qp, *Kp, *Vp, *Op;
    cudaGetSymbolAddress((void**)&Qp, g_Q);
    cudaGetSymbolAddress((void**)&Kp, g_K);
    cudaGetSymbolAddress((void**)&Vp, g_V);
    cudaGetSymbolAddress((void**)&Op, g_O);
    __nv_bfloat16 *xh, *xl, *ch, *cl, *oh, *ol, *wh, *wl;
    cudaGetSymbolAddress((void**)&xh, g_xh); cudaGetSymbolAddress((void**)&xl, g_xl);
    cudaGetSymbolAddress((void**)&ch, g_ch); cudaGetSymbolAddress((void**)&cl, g_cl);
    cudaGetSymbolAddress((void**)&oh, g_oh); cudaGetSymbolAddress((void**)&ol, g_ol);
    cudaGetSymbolAddress((void**)&wh, g_wh); cudaGetSymbolAddress((void**)&wl, g_wl);

    cudaFuncSetAttribute(hmma_gemm, cudaFuncAttributeMaxDynamicSharedMemorySize, GEMM_SMEM);

    const int NE = ROWS_ * D_;

    split_kernel<<<(NE + 255) / 256, 256>>>(x,   xh, xl, NE);
    split_kernel<<<(NE + 255) / 256, 256>>>(ctx, ch, cl, NE);
    wsplit_t_kernel<<<dim3(32, 32), dim3(32, 32)>>>(Wq, wh + 0 * D_ * D_, wl + 0 * D_ * D_);
    wsplit_t_kernel<<<dim3(32, 32), dim3(32, 32)>>>(Wk, wh + 1 * D_ * D_, wl + 1 * D_ * D_);
    wsplit_t_kernel<<<dim3(32, 32), dim3(32, 32)>>>(Wv, wh + 2 * D_ * D_, wl + 2 * D_ * D_);
    wsplit_t_kernel<<<dim3(32, 32), dim3(32, 32)>>>(Wo, wh + 3 * D_ * D_, wl + 3 * D_ * D_);

    dim3 ggrid(D_ / 128, ROWS_ / 128);   // (8, 32)
    hmma_gemm<<<ggrid, 256, GEMM_SMEM>>>(xh, xl, wh + 0 * D_ * D_, wl + 0 * D_ * D_, nullptr, Qp);
    hmma_gemm<<<ggrid, 256, GEMM_SMEM>>>(ch, cl, wh + 1 * D_ * D_, wl + 1 * D_ * D_, nullptr, Kp);
    hmma_gemm<<<ggrid, 256, GEMM_SMEM>>>(ch, cl, wh + 2 * D_ * D_, wl + 2 * D_ * D_, nullptr, Vp);

    attn_kernel<<<dim3(N_ / 128, H_, B_), 128>>>();

    split_kernel<<<(NE + 255) / 256, 256>>>(Op, oh, ol, NE);
    hmma_gemm<<<ggrid, 256, GEMM_SMEM>>>(oh, ol, wh + 3 * D_ * D_, wl + 3 * D_ * D_, bo, out);
}

// round 5
// speedup vs baseline: 2.8017x; 2.1396x over previous
#include <cuda_runtime.h>
#include <cuda_bf16.h>
#include <cstdint>

// ---------------------------------------------------------------------------
// Problem constants
// ---------------------------------------------------------------------------
#define B_  2
#define N_  2048
#define M_  2048
#define D_  1024
#define H_  16
#define DH_ 64
#define ROWS_ (B_ * N_)   // 4096
// softmax in log2 domain: Q pre-scaled by DH^-0.5 * log2(e)
#define QSCALE_ 0.180336880111f

// ---------------------------------------------------------------------------
// Portable PTX helpers (sm_80+ features, valid at compute_103)
// ---------------------------------------------------------------------------
__device__ __forceinline__ uint32_t smem_u32(const void* p) {
    uint32_t a;
    asm("{ .reg .u64 t; cvta.to.shared.u64 t, %1; cvt.u32.u64 %0, t; }" : "=r"(a) : "l"(p));
    return a;
}
#define CP_ASYNC16(sa, ga) \
    asm volatile("cp.async.cg.shared.global [%0], [%1], 16;" :: "r"(sa), "l"(ga))
#define CP_COMMIT() asm volatile("cp.async.commit_group;" ::: "memory")
#define CP_WAIT(n)  asm volatile("cp.async.wait_group %0;" :: "n"(n) : "memory")

__device__ __forceinline__ void ldsm_x4(uint32_t* r, uint32_t addr) {
    asm volatile("ldmatrix.sync.aligned.m8n8.x4.shared.b16 {%0,%1,%2,%3}, [%4];"
                 : "=r"(r[0]), "=r"(r[1]), "=r"(r[2]), "=r"(r[3]) : "r"(addr));
}
__device__ __forceinline__ void ldsm_x4_t(uint32_t* r, uint32_t addr) {
    asm volatile("ldmatrix.sync.aligned.m8n8.x4.trans.shared.b16 {%0,%1,%2,%3}, [%4];"
                 : "=r"(r[0]), "=r"(r[1]), "=r"(r[2]), "=r"(r[3]) : "r"(addr));
}
__device__ __forceinline__ void mma16816(float* c, const uint32_t* a, const uint32_t* b) {
    asm volatile(
        "mma.sync.aligned.m16n8k16.row.col.f32.bf16.bf16.f32 "
        "{%0,%1,%2,%3}, {%4,%5,%6,%7}, {%8,%9}, {%0,%1,%2,%3};"
        : "+f"(c[0]), "+f"(c[1]), "+f"(c[2]), "+f"(c[3])
        : "r"(a[0]), "r"(a[1]), "r"(a[2]), "r"(a[3]), "r"(b[0]), "r"(b[1]));
}

// fast 2^x on fma/alu pipes (no MUFU): magic-number round + degree-5 poly
__device__ __forceinline__ float exp2f_fast(float x) {
    x = fmaxf(x, -100.0f);
    float t = x + 12582912.0f;                 // round-to-nearest integer
    float r = x - (t - 12582912.0f);           // r in [-0.5, 0.5]
    float p = 1.3333558146e-3f;
    p = fmaf(p, r, 9.6181291076e-3f);
    p = fmaf(p, r, 5.5504108664e-2f);
    p = fmaf(p, r, 2.4022650696e-1f);
    p = fmaf(p, r, 6.9314718056e-1f);
    p = fmaf(p, r, 1.0f);
    return __int_as_float(__float_as_int(p) + (__float_as_int(t) << 23));
}

// pack two floats into bf16x2 hi + bf16x2 lo (split)
__device__ __forceinline__ void pack_hl(float x, float y, uint32_t& h, uint32_t& lo) {
    __nv_bfloat162 hv = __floats2bfloat162_rn(x, y);
    float hx = __bfloat162float(hv.x), hy = __bfloat162float(hv.y);
    __nv_bfloat162 lv = __floats2bfloat162_rn(x - hx, y - hy);
    h  = *reinterpret_cast<uint32_t*>(&hv);
    lo = *reinterpret_cast<uint32_t*>(&lv);
}

// ---------------------------------------------------------------------------
// Scratch (__device__ globals)
// ---------------------------------------------------------------------------
__device__ __nv_bfloat16 g_qh[ROWS_ * D_], g_ql[ROWS_ * D_];   // Q (scaled) hi/lo
__device__ __nv_bfloat16 g_kh[ROWS_ * D_], g_kl[ROWS_ * D_];
__device__ __nv_bfloat16 g_vh[ROWS_ * D_], g_vl[ROWS_ * D_];
__device__ __nv_bfloat16 g_oh[ROWS_ * D_], g_ol[ROWS_ * D_];   // attention out hi/lo
__device__ __nv_bfloat16 g_xh[ROWS_ * D_], g_xl[ROWS_ * D_];
__device__ __nv_bfloat16 g_ch[ROWS_ * D_], g_cl[ROWS_ * D_];
__device__ __nv_bfloat16 g_wh[4][D_ * D_], g_wl[4][D_ * D_];   // q,k,v,o transposed [n][k]

// ---------------------------------------------------------------------------
// fp32 -> bf16 hi/lo split: x and ctx in one launch (blockIdx.y selects)
// ---------------------------------------------------------------------------
__global__ void split2_kernel(const float* __restrict__ a, const float* __restrict__ b,
                              __nv_bfloat16* __restrict__ ah, __nv_bfloat16* __restrict__ al,
                              __nv_bfloat16* __restrict__ bh, __nv_bfloat16* __restrict__ bl,
                              int n)
{
    int i = blockIdx.x * blockDim.x + threadIdx.x;
    if (i >= n) return;
    const float* s = blockIdx.y ? b : a;
    __nv_bfloat16* dh = blockIdx.y ? bh : ah;
    __nv_bfloat16* dl = blockIdx.y ? bl : al;
    float v = s[i];
    __nv_bfloat16 hv = __float2bfloat16(v);
    dh[i] = hv;
    dl[i] = __float2bfloat16(v - __bfloat162float(hv));
}

// fp32 W[k][n] -> bf16 hi/lo transposed out[n][k]; blockIdx.z selects weight
__global__ void wsplit_t_kernel(const float* __restrict__ W0, const float* __restrict__ W1,
                                const float* __restrict__ W2, const float* __restrict__ W3,
                                __nv_bfloat16* __restrict__ hi, __nv_bfloat16* __restrict__ lo)
{
    __shared__ float tile[32][33];
    const float* W = (blockIdx.z == 0) ? W0 : (blockIdx.z == 1) ? W1 : (blockIdx.z == 2) ? W2 : W3;
    size_t zo = (size_t)blockIdx.z * D_ * D_;
    int n0 = blockIdx.x * 32, k0 = blockIdx.y * 32;
    tile[threadIdx.y][threadIdx.x] = W[(size_t)(k0 + threadIdx.y) * D_ + n0 + threadIdx.x];
    __syncthreads();
    float a = tile[threadIdx.x][threadIdx.y];
    __nv_bfloat16 h = __float2bfloat16(a);
    size_t o = zo + (size_t)(n0 + threadIdx.y) * D_ + k0 + threadIdx.x;
    hi[o] = h;
    lo[o] = __float2bfloat16(a - __bfloat162float(h));
}

// ---------------------------------------------------------------------------
// HMMA GEMM: C[4096,1024] = A @ B^T (B stored [n][k]); bf16 split-3, fp32 acc
// CTA 128x128, 8 warps (32x64 warp tile), K-stage 32, cp.async double buffer.
// MODE 0: fp32 out + bias.  MODE 1: bf16 hi/lo out, scaled.
// ---------------------------------------------------------------------------
#define NSTG (D_ / 32)
#define ARR_STRIDE 10240
#define STAGE_STRIDE (4 * ARR_STRIDE)
#define GEMM_SMEM (2 * STAGE_STRIDE)

template <int MODE>
__global__ __launch_bounds__(256) void hmma_gemm(
    const __nv_bfloat16* __restrict__ Ah_g, const __nv_bfloat16* __restrict__ Al_g,
    const __nv_bfloat16* __restrict__ Bh_g, const __nv_bfloat16* __restrict__ Bl_g,
    const float* __restrict__ bias, float scale,
    float* __restrict__ Cf,
    __nv_bfloat16* __restrict__ Ch, __nv_bfloat16* __restrict__ Cl)
{
    extern __shared__ char smem[];
    const uint32_t sb = smem_u32(smem);
    const int t = threadIdx.x;
    const int l = t & 31;
    const int wid = t >> 5;
    const int row0 = blockIdx.y * 128;
    const int col0 = blockIdx.x * 128;
    const int wr0 = (wid & 3) * 32;
    const int wc0 = (wid >> 2) * 64;

    float acc[2][8][4];
    #pragma unroll
    for (int i = 0; i < 2; i++)
        #pragma unroll
        for (int j = 0; j < 8; j++)
            #pragma unroll
            for (int k = 0; k < 4; k++) acc[i][j][k] = 0.f;

    auto load_stage = [&](int s) {
        const int k0 = s * 32;
        const uint32_t sbase = sb + (s & 1) * STAGE_STRIDE;
        #pragma unroll
        for (int i = 0; i < 8; i++) {
            int idx = i * 256 + t;
            int arr = idx >> 9;
            int rem = idx & 511;
            int row = rem >> 2;
            int ch  = rem & 3;
            const __nv_bfloat16* g;
            if (arr == 0)      g = Ah_g + (size_t)(row0 + row) * D_ + k0 + ch * 8;
            else if (arr == 1) g = Al_g + (size_t)(row0 + row) * D_ + k0 + ch * 8;
            else if (arr == 2) g = Bh_g + (size_t)(col0 + row) * D_ + k0 + ch * 8;
            else               g = Bl_g + (size_t)(col0 + row) * D_ + k0 + ch * 8;
            CP_ASYNC16(sbase + arr * ARR_STRIDE + row * 80 + ch * 16, g);
        }
        CP_COMMIT();
    };

    load_stage(0);

    for (int s = 0; s < NSTG; s++) {
        if (s + 1 < NSTG) { load_stage(s + 1); CP_WAIT(1); }
        else              { CP_WAIT(0); }
        __syncthreads();

        const uint32_t base = sb + (s & 1) * STAGE_STRIDE;
        const uint32_t aAh = base;
        const uint32_t aAl = base + ARR_STRIDE;
        const uint32_t aBh = base + 2 * ARR_STRIDE;
        const uint32_t aBl = base + 3 * ARR_STRIDE;

        #pragma unroll
        for (int ks = 0; ks < 2; ks++) {
            uint32_t ah[2][4], al[2][4], bh[8][2], bl[8][2];
            {
                int ar = wr0 + (l & 15);
                int ac = 2 * ks + (l >> 4);
                ldsm_x4(ah[0], aAh + (uint32_t)(ar * 80 + ac * 16));
                ldsm_x4(ah[1], aAh + (uint32_t)((ar + 16) * 80 + ac * 16));
                ldsm_x4(al[0], aAl + (uint32_t)(ar * 80 + ac * 16));
                ldsm_x4(al[1], aAl + (uint32_t)((ar + 16) * 80 + ac * 16));
            }
            {
                int br = wc0 + ((l >> 4) << 3) + (l & 7);
                int bc = 2 * ks + ((l >> 3) & 1);
                #pragma unroll
                for (int nt2 = 0; nt2 < 4; nt2++) {
                    uint32_t r[4];
                    ldsm_x4(r, aBh + (uint32_t)((br + nt2 * 16) * 80 + bc * 16));
                    bh[2 * nt2][0] = r[0]; bh[2 * nt2][1] = r[1];
                    bh[2 * nt2 + 1][0] = r[2]; bh[2 * nt2 + 1][1] = r[3];
                    ldsm_x4(r, aBl + (uint32_t)((br + nt2 * 16) * 80 + bc * 16));
                    bl[2 * nt2][0] = r[0]; bl[2 * nt2][1] = r[1];
                    bl[2 * nt2 + 1][0] = r[2]; bl[2 * nt2 + 1][1] = r[3];
                }
            }
            #pragma unroll
            for (int mt = 0; mt < 2; mt++)
                #pragma unroll
                for (int nt = 0; nt < 8; nt++) {
                    mma16816(acc[mt][nt], ah[mt], bh[nt]);
                    mma16816(acc[mt][nt], ah[mt], bl[nt]);
                    mma16816(acc[mt][nt], al[mt], bh[nt]);
                }
        }
        __syncthreads();
    }

    #pragma unroll
    for (int mt = 0; mt < 2; mt++)
        #pragma unroll
        for (int nt = 0; nt < 8; nt++) {
            int m = row0 + wr0 + mt * 16 + (l >> 2);
            int n = col0 + wc0 + nt * 8 + (l & 3) * 2;
            if (MODE == 0) {
                float bx = 0.f, by = 0.f;
                if (bias != nullptr) { bx = bias[n]; by = bias[n + 1]; }
                *reinterpret_cast<float2*>(&Cf[(size_t)m * D_ + n]) =
                    make_float2(acc[mt][nt][0] + bx, acc[mt][nt][1] + by);
                *reinterpret_cast<float2*>(&Cf[(size_t)(m + 8) * D_ + n]) =
                    make_float2(acc[mt][nt][2] + bx, acc[mt][nt][3] + by);
            } else {
                uint32_t hh, ll;
                pack_hl(acc[mt][nt][0] * scale, acc[mt][nt][1] * scale, hh, ll);
                *reinterpret_cast<uint32_t*>(&Ch[(size_t)m * D_ + n]) = hh;
                *reinterpret_cast<uint32_t*>(&Cl[(size_t)m * D_ + n]) = ll;
                pack_hl(acc[mt][nt][2] * scale, acc[mt][nt][3] * scale, hh, ll);
                *reinterpret_cast<uint32_t*>(&Ch[(size_t)(m + 8) * D_ + n]) = hh;
                *reinterpret_cast<uint32_t*>(&Cl[(size_t)(m + 8) * D_ + n]) = ll;
            }
        }
}

// ---------------------------------------------------------------------------
// HMMA flash attention. CTA = 128 queries x one (b,h). 8 warps, 16 rows each.
// Key tiles of 64; K/V (hi+lo) double-buffered via cp.async.
// Scores in log2 domain (Q pre-scaled); exp2 via FMA polynomial.
// ---------------------------------------------------------------------------
#define AKT 64
#define KROW 144                 // 64 bf16 = 128B data, padded to 144B
#define KB (AKT * KROW)          // 9216
#define ASTG (4 * KB)            // 36864
#define ATT_SMEM (2 * ASTG)      // 73728
#define NSKV (M_ / AKT)          // 32

__global__ __launch_bounds__(256) void attn_mma()
{
    extern __shared__ char smem[];
    const uint32_t sb = smem_u32(smem);
    const int t = threadIdx.x;
    const int l = t & 31;
    const int w = t >> 5;
    const int q0 = blockIdx.x * 128;
    const int h  = blockIdx.y;
    const int b  = blockIdx.z;
    const size_t headoff = (size_t)h * DH_;

    // ---- stage Q (128x64 hi/lo) through smem, ldmatrix into registers
    #pragma unroll
    for (int i = 0; i < 4; i++) {
        int idx = i * 256 + t;          // 0..1023
        int row = idx >> 3, ch = idx & 7;
        size_t g = (size_t)(b * N_ + q0 + row) * D_ + headoff + ch * 8;
        CP_ASYNC16(sb + row * KROW + ch * 16, g_qh + g);
        CP_ASYNC16(sb + 18432 + row * KROW + ch * 16, g_ql + g);
    }
    CP_COMMIT();
    CP_WAIT(0);
    __syncthreads();

    uint32_t qh[4][4], ql[4][4];
    {
        int ar = w * 16 + (l & 15);
        #pragma unroll
        for (int ks = 0; ks < 4; ks++) {
            ldsm_x4(qh[ks], sb + (uint32_t)(ar * KROW + ks * 32 + (l >> 4) * 16));
            ldsm_x4(ql[ks], sb + 18432 + (uint32_t)(ar * KROW + ks * 32 + (l >> 4) * 16));
        }
    }
    __syncthreads();   // done reading Q region before KV pipeline overwrites it

    float o[8][4];
    #pragma unroll
    for (int j = 0; j < 8; j++)
        #pragma unroll
        for (int i = 0; i < 4; i++) o[j][i] = 0.f;
    float m0 = -1e30f, m1 = -1e30f, ls0 = 0.f, ls1 = 0.f;

    auto load_kv = [&](int s) {
        const int mk = s * AKT;
        const uint32_t base = sb + (s & 1) * ASTG;
        #pragma unroll
        for (int i = 0; i < 8; i++) {
            int arr = i >> 1;                       // 0:Kh 1:Kl 2:Vh 3:Vl
            int rem = (i & 1) * 256 + t;            // 0..511
            int row = rem >> 3, ch = rem & 7;
            size_t g = (size_t)(b * M_ + mk + row) * D_ + headoff + ch * 8;
            const __nv_bfloat16* src = (arr == 0) ? g_kh : (arr == 1) ? g_kl
                                      : (arr == 2) ? g_vh : g_vl;
            CP_ASYNC16(base + arr * KB + row * KROW + ch * 16, src + g);
        }
        CP_COMMIT();
    };

    load_kv(0);

    for (int s = 0; s < NSKV; s++) {
        if (s + 1 < NSKV) { load_kv(s + 1); CP_WAIT(1); }
        else              { CP_WAIT(0); }
        __syncthreads();

        const uint32_t kh = sb + (s & 1) * ASTG;
        const uint32_t kl = kh + KB;
        const uint32_t vh = kh + 2 * KB;
        const uint32_t vl = kh + 3 * KB;

        // ---- S = Qh*Kh + Qh*Kl + Ql*Kh  (128x64, per-warp 16x64)
        float sc[8][4];
        #pragma unroll
        for (int j = 0; j < 8; j++)
            #pragma unroll
            for (int i = 0; i < 4; i++) sc[j][i] = 0.f;

        #pragma unroll
        for (int ks = 0; ks < 4; ks++) {
            int br = ((l >> 4) << 3) + (l & 7);
            int bcb = ks * 32 + ((l >> 3) & 1) * 16;
            #pragma unroll
            for (int nt2 = 0; nt2 < 4; nt2++) {
                uint32_t rh[4], rl[4];
                ldsm_x4(rh, kh + (uint32_t)((nt2 * 16 + br) * KROW + bcb));
                ldsm_x4(rl, kl + (uint32_t)((nt2 * 16 + br) * KROW + bcb));
                mma16816(sc[2 * nt2],     qh[ks], rh + 0);
                mma16816(sc[2 * nt2 + 1], qh[ks], rh + 2);
                mma16816(sc[2 * nt2],     qh[ks], rl + 0);
                mma16816(sc[2 * nt2 + 1], qh[ks], rl + 2);
                mma16816(sc[2 * nt2],     ql[ks], rh + 0);
                mma16816(sc[2 * nt2 + 1], ql[ks], rh + 2);
            }
        }

        // ---- online softmax (log2 domain)
        float mx0 = -1e30f, mx1 = -1e30f;
        #pragma unroll
        for (int j = 0; j < 8; j++) {
            mx0 = fmaxf(mx0, fmaxf(sc[j][0], sc[j][1]));
            mx1 = fmaxf(mx1, fmaxf(sc[j][2], sc[j][3]));
        }
        mx0 = fmaxf(mx0, __shfl_xor_sync(0xffffffffu, mx0, 1));
        mx0 = fmaxf(mx0, __shfl_xor_sync(0xffffffffu, mx0, 2));
        mx1 = fmaxf(mx1, __shfl_xor_sync(0xffffffffu, mx1, 1));
        mx1 = fmaxf(mx1, __shfl_xor_sync(0xffffffffu, mx1, 2));
        float mn0 = fmaxf(m0, mx0), mn1 = fmaxf(m1, mx1);
        float c0 = exp2f_fast(m0 - mn0), c1 = exp2f_fast(m1 - mn1);
        m0 = mn0; m1 = mn1;

        float ps0 = 0.f, ps1 = 0.f;
        #pragma unroll
        for (int j = 0; j < 8; j++) {
            sc[j][0] = exp2f_fast(sc[j][0] - mn0); ps0 += sc[j][0];
            sc[j][1] = exp2f_fast(sc[j][1] - mn0); ps0 += sc[j][1];
            sc[j][2] = exp2f_fast(sc[j][2] - mn1); ps1 += sc[j][2];
            sc[j][3] = exp2f_fast(sc[j][3] - mn1); ps1 += sc[j][3];
        }
        ps0 += __shfl_xor_sync(0xffffffffu, ps0, 1);
        ps0 += __shfl_xor_sync(0xffffffffu, ps0, 2);
        ps1 += __shfl_xor_sync(0xffffffffu, ps1, 1);
        ps1 += __shfl_xor_sync(0xffffffffu, ps1, 2);
        ls0 = ls0 * c0 + ps0;
        ls1 = ls1 * c1 + ps1;
        #pragma unroll
        for (int j = 0; j < 8; j++) {
            o[j][0] *= c0; o[j][1] *= c0;
            o[j][2] *= c1; o[j][3] *= c1;
        }

        // ---- O += (Ph+Pl) @ (Vh+Vl)  (3 terms)
        #pragma unroll
        for (int kv = 0; kv < 4; kv++) {
            uint32_t aPh[4], aPl[4];
            pack_hl(sc[2 * kv][0],     sc[2 * kv][1],     aPh[0], aPl[0]);
            pack_hl(sc[2 * kv][2],     sc[2 * kv][3],     aPh[1], aPl[1]);
            pack_hl(sc[2 * kv + 1][0], sc[2 * kv + 1][1], aPh[2], aPl[2]);
            pack_hl(sc[2 * kv + 1][2], sc[2 * kv + 1][3], aPh[3], aPl[3]);
            int key = kv * 16 + ((l >> 3) & 1) * 8 + (l & 7);
            #pragma unroll
            for (int nd2 = 0; nd2 < 4; nd2++) {
                uint32_t vbh[4], vbl[4];
                uint32_t va = (uint32_t)(key * KROW + nd2 * 32 + (l >> 4) * 16);
                ldsm_x4_t(vbh, vh + va);
                ldsm_x4_t(vbl, vl + va);
                mma16816(o[2 * nd2],     aPh, vbh + 0);
                mma16816(o[2 * nd2 + 1], aPh, vbh + 2);
                mma16816(o[2 * nd2],     aPh, vbl + 0);
                mma16816(o[2 * nd2 + 1], aPh, vbl + 2);
                mma16816(o[2 * nd2],     aPl, vbh + 0);
                mma16816(o[2 * nd2 + 1], aPl, vbh + 2);
            }
        }
        __syncthreads();   // all warps done reading stage s before it is refilled
    }

    // ---- normalize + write bf16 hi/lo
    float inv0 = 1.f / ls0, inv1 = 1.f / ls1;
    int r0 = q0 + w * 16 + (l >> 2);
    int r1 = r0 + 8;
    size_t base0 = (size_t)(b * N_ + r0) * D_ + headoff;
    size_t base1 = (size_t)(b * N_ + r1) * D_ + headoff;
    #pragma unroll
    for (int nd = 0; nd < 8; nd++) {
        int c = nd * 8 + (l & 3) * 2;
        uint32_t hh, ll;
        pack_hl(o[nd][0] * inv0, o[nd][1] * inv0, hh, ll);
        *reinterpret_cast<uint32_t*>(&g_oh[base0 + c]) = hh;
        *reinterpret_cast<uint32_t*>(&g_ol[base0 + c]) = ll;
        pack_hl(o[nd][2] * inv1, o[nd][3] * inv1, hh, ll);
        *reinterpret_cast<uint32_t*>(&g_oh[base1 + c]) = hh;
        *reinterpret_cast<uint32_t*>(&g_ol[base1 + c]) = ll;
    }
}

// ---------------------------------------------------------------------------
// Launch
// ---------------------------------------------------------------------------
extern "C" void kernel_launch(void* const* d_in, const int* in_sizes, int n_in,
                              void* d_out, int out_size)
{
    const float* x   = (const float*)d_in[0];
    const float* ctx = (const float*)d_in[1];
    const float* Wq  = (const float*)d_in[2];
    const float* Wk  = (const float*)d_in[3];
    const float* Wv  = (const float*)d_in[4];
    const float* Wo  = (const float*)d_in[5];
    const float* bo  = (const float*)d_in[6];
    float* out = (float*)d_out;

    __nv_bfloat16 *qh, *ql, *kh, *kl, *vh, *vl, *oh, *ol, *xh, *xl, *ch, *cl, *wh, *wl;
    cudaGetSymbolAddress((void**)&qh, g_qh); cudaGetSymbolAddress((void**)&ql, g_ql);
    cudaGetSymbolAddress((void**)&kh, g_kh); cudaGetSymbolAddress((void**)&kl, g_kl);
    cudaGetSymbolAddress((void**)&vh, g_vh); cudaGetSymbolAddress((void**)&vl, g_vl);
    cudaGetSymbolAddress((void**)&oh, g_oh); cudaGetSymbolAddress((void**)&ol, g_ol);
    cudaGetSymbolAddress((void**)&xh, g_xh); cudaGetSymbolAddress((void**)&xl, g_xl);
    cudaGetSymbolAddress((void**)&ch, g_ch); cudaGetSymbolAddress((void**)&cl, g_cl);
    cudaGetSymbolAddress((void**)&wh, g_wh); cudaGetSymbolAddress((void**)&wl, g_wl);

    cudaFuncSetAttribute(hmma_gemm<0>, cudaFuncAttributeMaxDynamicSharedMemorySize, GEMM_SMEM);
    cudaFuncSetAttribute(hmma_gemm<1>, cudaFuncAttributeMaxDynamicSharedMemorySize, GEMM_SMEM);
    cudaFuncSetAttribute(attn_mma, cudaFuncAttributeMaxDynamicSharedMemorySize, ATT_SMEM);

    const int NE = ROWS_ * D_;
    const size_t WSZ = (size_t)D_ * D_;

    split2_kernel<<<dim3((NE + 255) / 256, 2), 256>>>(x, ctx, xh, xl, ch, cl, NE);
    wsplit_t_kernel<<<dim3(32, 32, 4), dim3(32, 32)>>>(Wq, Wk, Wv, Wo, wh, wl);

    dim3 ggrid(D_ / 128, ROWS_ / 128);
    hmma_gemm<1><<<ggrid, 256, GEMM_SMEM>>>(xh, xl, wh + 0 * WSZ, wl + 0 * WSZ,
                                            nullptr, QSCALE_, nullptr, qh, ql);
    hmma_gemm<1><<<ggrid, 256, GEMM_SMEM>>>(ch, cl, wh + 1 * WSZ, wl + 1 * WSZ,
                                            nullptr, 1.0f, nullptr, kh, kl);
    hmma_gemm<1><<<ggrid, 256, GEMM_SMEM>>>(ch, cl, wh + 2 * WSZ, wl + 2 * WSZ,
                                            nullptr, 1.0f, nullptr, vh, vl);

    attn_mma<<<dim3(N_ / 128, H_, B_), 256, ATT_SMEM>>>();

    hmma_gemm<0><<<ggrid, 256, GEMM_SMEM>>>(oh, ol, wh + 3 * WSZ, wl + 3 * WSZ,
                                            bo, 1.0f, out, nullptr, nullptr);
}